// round 2
// baseline (speedup 1.0000x reference)
#include <cuda_runtime.h>
#include <math.h>

// ---------------------------------------------------------------------------
// Problem constants
// ---------------------------------------------------------------------------
#define NTOK 32          // AVGF tokens
#define MDIM 2048        // model dim
#define HDIM 8192        // mlp hidden
#define KC   64          // K-chunk per smem stage
#define TN   32          // N-tile per CTA
#define SPAD 34          // smem row pad (even -> keeps float2 alignment, 2-way STS conflicts only)

typedef unsigned long long ull;

// f32x2 packed math (Blackwell FFMA2 path — only reachable via PTX fma.rn.f32x2)
__device__ __forceinline__ ull fma2(ull a, ull b, ull c) {
    ull d;
    asm("fma.rn.f32x2 %0, %1, %2, %3;" : "=l"(d) : "l"(a), "l"(b), "l"(c));
    return d;
}
__device__ __forceinline__ ull pack_dup(float w) {
    unsigned u = __float_as_uint(w);
    ull d;
    asm("mov.b64 %0, {%1, %1};" : "=l"(d) : "r"(u));
    return d;
}
__device__ __forceinline__ void unpack2(ull v, float& lo, float& hi) {
    unsigned a, b;
    asm("mov.b64 {%0, %1}, %2;" : "=r"(a), "=r"(b) : "l"(v));
    lo = __uint_as_float(a);
    hi = __uint_as_float(b);
}

// ---------------------------------------------------------------------------
// Scratch (no allocation allowed -> __device__ globals)
// ---------------------------------------------------------------------------
__device__ float g_xcf [NTOK * MDIM];
__device__ float g_s   [NTOK * MDIM];
__device__ float g_vcum[NTOK * MDIM];
__device__ float g_s2  [NTOK * MDIM];
__device__ float g_h   [NTOK * HDIM];
__device__ float g_part[4 * NTOK * MDIM];   // split-K partial sums (max 4 splits)
__device__ float g_st1 [NTOK * 2];          // LN1 stats (mean, rstd) per token
__device__ float g_st2 [NTOK * 2];          // LN2 stats

// ---------------------------------------------------------------------------
// K1: x (16,128,512) -> xcf[32][2048];  xcf[i][b*16+a] = mean_t x[a][b][i*16+t]
// ---------------------------------------------------------------------------
__global__ void reduce_x_k(const float* __restrict__ x, float* __restrict__ xcf) {
    int o = blockIdx.x * blockDim.x + threadIdx.x;     // 65536 outputs
    int i = o >> 11;
    int m = o & 2047;
    int b = m >> 4;
    int a = m & 15;
    const float* p = x + a * (128 * 512) + b * 512 + i * 16;
    float s = 0.f;
#pragma unroll
    for (int t = 0; t < 16; ++t) s += p[t];
    xcf[o] = s * (1.f / 16.f);
}

// ---------------------------------------------------------------------------
// GEMM: C[32][N] (+)= X[32][K] @ W[N][K]^T
//   XF: 0 none | 1 LN(x)        (x-m)*r*g+b          | 2 LN(x)+x
//   EPI: 0 store split-K partial at C + blkIdx.y*NTOK*N | 3 +bias then exact GELU, direct store
// grid: (N/TN, SK).  Each CTA covers its K-slice [blkIdx.y*K/SK, ...).
// Layout: 256 thr; lane = n within tile (coalesced stores, conflict-free W LDS),
//         warp w owns tokens 4w..4w+3 (f32x2 pairs of tokens).
// ---------------------------------------------------------------------------
template<int XF, int EPI>
__global__ void gemm_k(const float* __restrict__ X, const float* __restrict__ W,
                       float* __restrict__ C, int N, int K,
                       const float* __restrict__ stats, const float* __restrict__ lg,
                       const float* __restrict__ lb, const float* __restrict__ bias)
{
    __shared__ __align__(16) float Xs[KC][SPAD];
    __shared__ __align__(16) float Ws[KC][SPAD];

    const int tid  = threadIdx.x;
    const int lane = tid & 31;
    const int w    = tid >> 5;
    const int t0   = w * 4;
    const int n0   = blockIdx.x * TN;
    const int klen = K / gridDim.y;
    const int kbeg = blockIdx.y * klen;

    const int lr = tid >> 6;      // 0..3  (row within load pass)
    const int lk = tid & 63;      // k within chunk

    ull a01 = 0ull, a23 = 0ull;

    for (int k0 = kbeg; k0 < kbeg + klen; k0 += KC) {
        __syncthreads();
        // --- stage X chunk (with fused LN transform) ---
#pragma unroll
        for (int p = 0; p < 8; ++p) {
            int t = p * 4 + lr;
            float v = X[t * K + k0 + lk];
            if (XF) {
                float m  = stats[2 * t];
                float r  = stats[2 * t + 1];
                float xn = (v - m) * r * lg[k0 + lk] + lb[k0 + lk];
                v = (XF == 2) ? (xn + v) : xn;
            }
            Xs[lk][t] = v;
        }
        // --- stage W chunk ---
#pragma unroll
        for (int p = 0; p < 8; ++p) {
            int n = p * 4 + lr;
            Ws[lk][n] = W[(n0 + n) * K + k0 + lk];
        }
        __syncthreads();
        // --- compute ---
#pragma unroll 32
        for (int kk = 0; kk < KC; ++kk) {
            ull wp  = pack_dup(Ws[kk][lane]);
            ull x01 = *(const ull*)&Xs[kk][t0];
            ull x23 = *(const ull*)&Xs[kk][t0 + 2];
            a01 = fma2(x01, wp, a01);
            a23 = fma2(x23, wp, a23);
        }
    }

    const int n = n0 + lane;
    float v[4];
    unpack2(a01, v[0], v[1]);
    unpack2(a23, v[2], v[3]);

    float* Cb = C;
    if (EPI == 0) Cb += (size_t)blockIdx.y * (NTOK * N);

#pragma unroll
    for (int j = 0; j < 4; ++j) {
        int t = t0 + j;
        float val = v[j];
        if (EPI == 3) {                       // +bias, exact GELU
            val += bias[n];
            val = 0.5f * val * (1.f + erff(val * 0.70710678118f));
        }
        Cb[t * N + n] = val;
    }
}

// ---------------------------------------------------------------------------
// prefix over tokens: vcum[i][k] = sum_{j<=i} (part0[j][k] + part1[j][k])
// ---------------------------------------------------------------------------
__global__ void prefix2_k(const float* __restrict__ parts, float* __restrict__ vc) {
    int k = blockIdx.x * blockDim.x + threadIdx.x;   // 2048
    float acc = 0.f;
    for (int i = 0; i < NTOK; ++i) {
        acc += parts[i * MDIM + k] + parts[NTOK * MDIM + i * MDIM + k];
        vc[i * MDIM + k] = acc;
    }
}

// ---------------------------------------------------------------------------
// fin_stats: combine SK split-K partials, apply MODE, write target row, and
// compute LayerNorm stats (mean, rstd) of the written row.
//   MODE 0: + bias[c]         (fc2 epilogue -> next s, LN1 stats)
//   MODE 1: + sinusoidal pos  (s0 epilogue, LN1 stats)
//   MODE 2: + resid[row][c]   (Wo epilogue -> s2, LN2 stats)
// one block per token row; N = 2048.
// ---------------------------------------------------------------------------
template<int SK, int MODE>
__global__ void fin_stats_k(const float* __restrict__ parts, const float* __restrict__ extra,
                            float* __restrict__ outp, float* __restrict__ st)
{
    const int row = blockIdx.x;
    float s = 0.f, q = 0.f;
    for (int c = threadIdx.x; c < MDIM; c += blockDim.x) {
        float v = 0.f;
#pragma unroll
        for (int p = 0; p < SK; ++p) v += parts[p * NTOK * MDIM + row * MDIM + c];
        if (MODE == 0) {
            v += extra[c];
        } else if (MODE == 1) {
            // bias[i, c] : even c -> sin(i * 10000^(-c/1024)), odd -> cos with (c-1)
            float iv  = exp2f(-(float)(c & ~1) * 0.012976281620653759f); // log2(1e4)/1024
            float ang = (float)row * iv;
            v += (c & 1) ? cosf(ang) : sinf(ang);
        } else {
            v += extra[row * MDIM + c];
        }
        outp[row * MDIM + c] = v;
        s += v;
        q += v * v;
    }
#pragma unroll
    for (int off = 16; off; off >>= 1) {
        s += __shfl_down_sync(0xffffffffu, s, off);
        q += __shfl_down_sync(0xffffffffu, q, off);
    }
    __shared__ float rs[8], rq[8];
    if ((threadIdx.x & 31) == 0) { rs[threadIdx.x >> 5] = s; rq[threadIdx.x >> 5] = q; }
    __syncthreads();
    if (threadIdx.x == 0) {
        float S = 0.f, Q = 0.f;
#pragma unroll
        for (int i = 0; i < 8; ++i) { S += rs[i]; Q += rq[i]; }
        float m   = S * (1.f / (float)MDIM);
        float var = Q * (1.f / (float)MDIM) - m * m;
        st[2 * row]     = m;
        st[2 * row + 1] = rsqrtf(var + 1e-5f);
    }
}

// ---------------------------------------------------------------------------
// launch
// ---------------------------------------------------------------------------
extern "C" void kernel_launch(void* const* d_in, const int* in_sizes, int n_in,
                              void* d_out, int out_size)
{
    const float* x      = (const float*)d_in[0];
    const float* weight = (const float*)d_in[1];
    // d_in[2] = Wq, d_in[3] = Wk : provably unused (softmax over singleton axis == 1)
    const float* Wv     = (const float*)d_in[4];
    const float* Wo     = (const float*)d_in[5];
    const float* ln1g   = (const float*)d_in[6];
    const float* ln1b   = (const float*)d_in[7];
    const float* ln2g   = (const float*)d_in[8];
    const float* ln2b   = (const float*)d_in[9];
    const float* fc1w   = (const float*)d_in[10];
    const float* fc1b   = (const float*)d_in[11];
    const float* fc2w   = (const float*)d_in[12];
    const float* fc2b   = (const float*)d_in[13];
    float* out = (float*)d_out;

    float *xcf, *sbuf, *vcum, *s2, *hbuf, *part, *st1, *st2;
    cudaGetSymbolAddress((void**)&xcf,  g_xcf);
    cudaGetSymbolAddress((void**)&sbuf, g_s);
    cudaGetSymbolAddress((void**)&vcum, g_vcum);
    cudaGetSymbolAddress((void**)&s2,   g_s2);
    cudaGetSymbolAddress((void**)&hbuf, g_h);
    cudaGetSymbolAddress((void**)&part, g_part);
    cudaGetSymbolAddress((void**)&st1,  g_st1);
    cudaGetSymbolAddress((void**)&st2,  g_st2);

    const int WSLAB = 8 * 256 * 2048;   // per-block slab in Wv / Wo (= 2048*2048)

    // xcf
    reduce_x_k<<<256, 256>>>(x, xcf);
    // s0 = xcf @ weight^T (split-K 2) ; then +pos bias, LN1 stats
    gemm_k<0, 0><<<dim3(MDIM / TN, 2), 256>>>(xcf, weight, part, MDIM, MDIM, 0, 0, 0, 0);
    fin_stats_k<2, 1><<<NTOK, 256>>>(part, nullptr, sbuf, st1);

    for (int a = 0; a < 3; ++a) {
        // V = LN1(s) @ Wv[a]^T   (split-K 2, partials)
        gemm_k<1, 0><<<dim3(MDIM / TN, 2), 256>>>(sbuf, Wv + a * WSLAB, part, MDIM, MDIM,
                                                  st1, ln1g, ln1b, 0);
        // vcum = token prefix-sum of V
        prefix2_k<<<MDIM / 256, 256>>>(part, vcum);
        // s2 = vcum @ Wo[a]^T + s   (split-K 2, residual in fin) ; LN2 stats
        gemm_k<0, 0><<<dim3(MDIM / TN, 2), 256>>>(vcum, Wo + a * WSLAB, part, MDIM, MDIM,
                                                  0, 0, 0, 0);
        fin_stats_k<2, 2><<<NTOK, 256>>>(part, sbuf, s2, st2);
        // h = gelu( (LN2(s2)+s2) @ fc1^T + b1 )   (256 CTAs, fully fused)
        gemm_k<2, 3><<<dim3(HDIM / TN, 1), 256>>>(s2, fc1w, hbuf, HDIM, MDIM,
                                                  st2, ln2g, ln2b, fc1b);
        // s_next = h @ fc2^T + b2   (split-K 4) ; last iter writes d_out
        gemm_k<0, 0><<<dim3(MDIM / TN, 4), 256>>>(hbuf, fc2w, part, MDIM, HDIM,
                                                  0, 0, 0, 0);
        fin_stats_k<4, 0><<<NTOK, 256>>>(part, fc2b, (a == 2) ? out : sbuf, st1);
    }
    (void)in_sizes; (void)n_in; (void)out_size;
}

// round 3
// speedup vs baseline: 3.1314x; 3.1314x over previous
#include <cuda_runtime.h>
#include <math.h>

// ---------------------------------------------------------------------------
// Problem constants
// ---------------------------------------------------------------------------
#define NTOK 32          // tokens (AVGF)
#define MDIM 2048        // model dim
#define HDIM 8192        // mlp hidden
#define KC   32          // K-chunk per smem stage

typedef unsigned long long ull;

// f32x2 packed math (Blackwell FFMA2 path — only reachable via PTX fma.rn.f32x2)
__device__ __forceinline__ ull fma2(ull a, ull b, ull c) {
    ull d;
    asm("fma.rn.f32x2 %0, %1, %2, %3;" : "=l"(d) : "l"(a), "l"(b), "l"(c));
    return d;
}
__device__ __forceinline__ ull pack_dup(float w) {
    unsigned u = __float_as_uint(w);
    ull d;
    asm("mov.b64 %0, {%1, %1};" : "=l"(d) : "r"(u));
    return d;
}
__device__ __forceinline__ void unpack2(ull v, float& lo, float& hi) {
    unsigned a, b;
    asm("mov.b64 {%0, %1}, %2;" : "=r"(a), "=r"(b) : "l"(v));
    lo = __uint_as_float(a);
    hi = __uint_as_float(b);
}

// ---------------------------------------------------------------------------
// Scratch (no allocation allowed -> __device__ globals)
// ---------------------------------------------------------------------------
__device__ float g_xcf [NTOK * MDIM];
__device__ float g_s   [NTOK * MDIM];
__device__ float g_v   [NTOK * MDIM];
__device__ float g_vcum[NTOK * MDIM];
__device__ float g_s2  [NTOK * MDIM];
__device__ float g_h   [NTOK * HDIM];
__device__ float g_part[64 * NTOK * MDIM];   // split-K partials (64*32*2048 == 16*32*8192)
__device__ float g_bs  [NTOK * 8 * 2];       // per-(row, col-chunk) sum / sumsq
__device__ float g_st1 [NTOK * 2];           // LN1 stats (mean, rstd)
__device__ float g_st2 [NTOK * 2];           // LN2 stats

// ---------------------------------------------------------------------------
// K1: x (16,128,512) -> xcf[32][2048];  xcf[i][b*16+a] = mean_t x[a][b][16i+t]
// ---------------------------------------------------------------------------
__global__ void reduce_x_k(const float* __restrict__ x, float* __restrict__ xcf) {
    int o = blockIdx.x * blockDim.x + threadIdx.x;     // 65536 outputs
    int i = o >> 11;
    int m = o & 2047;
    int b = m >> 4;
    int a = m & 15;
    const float* p = x + a * (128 * 512) + b * 512 + i * 16;
    float s = 0.f;
#pragma unroll
    for (int t = 0; t < 16; ++t) s += p[t];
    xcf[o] = s * (1.f / 16.f);
}

// ---------------------------------------------------------------------------
// GEMM: partials[slot][32][N] = X[32][K-slice] @ W[N][K]^T   (K-slice per slot)
//   XF: 0 none | 1 LN1(x) | 2 LN2(x)+x   (fused into the X smem staging)
// CTA: 128 threads; tile = 256 n-cols x 32 tokens. Thread owns 2 n-cols,
// all 32 tokens as 32 f32x2 accumulators (32 independent FMA chains).
// grid = (N/256, SK); K-slice = K/SK (multiple of KC).
// ---------------------------------------------------------------------------
template<int XF>
__global__ void __launch_bounds__(128) gemm2_k(
        const float* __restrict__ X, const float* __restrict__ W,
        float* __restrict__ C, int N, int K,
        const float* __restrict__ stats, const float* __restrict__ lg,
        const float* __restrict__ lb)
{
    __shared__ __align__(16) float Xs[KC][32];     // [kk][token]  4KB
    __shared__ float Ws[256 * 33];                  // [n][kk] pitch 33  (33.8KB)

    const int tid  = threadIdx.x;
    const int n0   = blockIdx.x * 256;
    const int klen = K / gridDim.y;
    const int kbeg = blockIdx.y * klen;

    ull accA[16], accB[16];
#pragma unroll
    for (int m = 0; m < 16; ++m) { accA[m] = 0ull; accB[m] = 0ull; }

    for (int k0 = kbeg; k0 < kbeg + klen; k0 += KC) {
        __syncthreads();
        // ---- stage X chunk: warp 0, lane = token; fused LN transform ----
        if (tid < 32) {
            const float* xr = X + (size_t)tid * K + k0;
            float mn = 0.f, rs = 0.f;
            if (XF) { mn = stats[2 * tid]; rs = stats[2 * tid + 1]; }
#pragma unroll
            for (int c = 0; c < KC; c += 4) {
                float4 v4 = *(const float4*)(xr + c);
                float vv[4] = {v4.x, v4.y, v4.z, v4.w};
#pragma unroll
                for (int e = 0; e < 4; ++e) {
                    float val = vv[e];
                    if (XF) {
                        float xn = (val - mn) * rs * lg[k0 + c + e] + lb[k0 + c + e];
                        val = (XF == 2) ? (xn + val) : xn;
                    }
                    Xs[c + e][tid] = val;
                }
            }
        }
        // ---- stage W chunk: 256 rows x 32 k, all threads, transposed store ----
#pragma unroll
        for (int p = 0; p < 16; ++p) {
            int rr = p * 16 + (tid >> 3);
            int cc = (tid & 7) * 4;
            float4 wv = *(const float4*)(W + (size_t)(n0 + rr) * K + k0 + cc);
            float* dst = &Ws[rr * 33 + cc];
            dst[0] = wv.x; dst[1] = wv.y; dst[2] = wv.z; dst[3] = wv.w;
        }
        __syncthreads();
        // ---- compute ----
#pragma unroll 4
        for (int kk = 0; kk < KC; ++kk) {
            ull wpA = pack_dup(Ws[tid * 33 + kk]);
            ull wpB = pack_dup(Ws[(tid + 128) * 33 + kk]);
#pragma unroll
            for (int j = 0; j < 8; ++j) {
                uint4 u = *(const uint4*)&Xs[kk][j * 4];
                ull x01, x23;
                asm("mov.b64 %0, {%1,%2};" : "=l"(x01) : "r"(u.x), "r"(u.y));
                asm("mov.b64 %0, {%1,%2};" : "=l"(x23) : "r"(u.z), "r"(u.w));
                accA[2 * j]     = fma2(x01, wpA, accA[2 * j]);
                accA[2 * j + 1] = fma2(x23, wpA, accA[2 * j + 1]);
                accB[2 * j]     = fma2(x01, wpB, accB[2 * j]);
                accB[2 * j + 1] = fma2(x23, wpB, accB[2 * j + 1]);
            }
        }
    }

    // ---- epilogue: write this slot's partial tile ----
    float* Cb = C + (size_t)blockIdx.y * ((size_t)NTOK * N);
    const int nA = n0 + tid;
    const int nB = nA + 128;
#pragma unroll
    for (int m = 0; m < 16; ++m) {
        float lo, hi;
        unpack2(accA[m], lo, hi);
        Cb[(size_t)(2 * m) * N + nA]     = lo;
        Cb[(size_t)(2 * m + 1) * N + nA] = hi;
        unpack2(accB[m], lo, hi);
        Cb[(size_t)(2 * m) * N + nB]     = lo;
        Cb[(size_t)(2 * m + 1) * N + nB] = hi;
    }
}

// ---------------------------------------------------------------------------
// combine: out[row][c] = sum_p parts[p][row][c] (+ MODE epilogue)
//   MODE 0: + bias[c]                      (+ LN stat partials)
//   MODE 1: + sinusoidal pos bias          (+ LN stat partials)
//   MODE 2: + extra[row][c] (residual)     (+ LN stat partials)
//   MODE 3: + bias[c], exact GELU          (no stats)
//   MODE 4: plain                          (no stats)
// grid = (N/256, 32 rows), 256 threads.
// ---------------------------------------------------------------------------
template<int SK, int MODE>
__global__ void combine_k(const float* __restrict__ parts, const float* __restrict__ extra,
                          float* __restrict__ outp, float* __restrict__ bsums, int N)
{
    const int row = blockIdx.y;
    const int c   = blockIdx.x * 256 + threadIdx.x;
    const size_t slot = (size_t)NTOK * N;
    const size_t base = (size_t)row * N + c;

    float v = 0.f;
#pragma unroll 16
    for (int p = 0; p < SK; ++p) v += parts[p * slot + base];

    if (MODE == 0) {
        v += extra[c];
    } else if (MODE == 1) {
        float iv  = exp2f(-(float)(c & ~1) * 0.012976281620653759f); // log2(1e4)/1024
        float ang = (float)row * iv;
        v += (c & 1) ? cosf(ang) : sinf(ang);
    } else if (MODE == 2) {
        v += extra[base];
    } else if (MODE == 3) {
        v += extra[c];
        v = 0.5f * v * (1.f + erff(v * 0.70710678118f));
    }
    outp[base] = v;

    if (MODE <= 2) {
        float s = v, q = v * v;
#pragma unroll
        for (int off = 16; off; off >>= 1) {
            s += __shfl_down_sync(0xffffffffu, s, off);
            q += __shfl_down_sync(0xffffffffu, q, off);
        }
        __shared__ float rs[8], rq[8];
        if ((threadIdx.x & 31) == 0) { rs[threadIdx.x >> 5] = s; rq[threadIdx.x >> 5] = q; }
        __syncthreads();
        if (threadIdx.x == 0) {
            float S = 0.f, Q = 0.f;
#pragma unroll
            for (int i = 0; i < 8; ++i) { S += rs[i]; Q += rq[i]; }
            bsums[(row * gridDim.x + blockIdx.x) * 2]     = S;
            bsums[(row * gridDim.x + blockIdx.x) * 2 + 1] = Q;
        }
    }
}

// finalize LN stats from 8 per-chunk partials per row (N=2048 rows only)
__global__ void stats_k(const float* __restrict__ bsums, float* __restrict__ st) {
    int row = threadIdx.x;   // 32 threads
    float S = 0.f, Q = 0.f;
#pragma unroll
    for (int i = 0; i < 8; ++i) {
        S += bsums[(row * 8 + i) * 2];
        Q += bsums[(row * 8 + i) * 2 + 1];
    }
    float m   = S * (1.f / (float)MDIM);
    float var = Q * (1.f / (float)MDIM) - m * m;
    st[2 * row]     = m;
    st[2 * row + 1] = rsqrtf(var + 1e-5f);
}

// token prefix-sum: vcum[i][k] = sum_{j<=i} V[j][k]
__global__ void prefix_k(const float* __restrict__ V, float* __restrict__ vc) {
    int k = blockIdx.x * 256 + threadIdx.x;   // 2048
    float acc = 0.f;
#pragma unroll
    for (int i = 0; i < NTOK; ++i) {
        acc += V[i * MDIM + k];
        vc[i * MDIM + k] = acc;
    }
}

// ---------------------------------------------------------------------------
// launch
// ---------------------------------------------------------------------------
extern "C" void kernel_launch(void* const* d_in, const int* in_sizes, int n_in,
                              void* d_out, int out_size)
{
    const float* x      = (const float*)d_in[0];
    const float* weight = (const float*)d_in[1];
    // d_in[2]=Wq, d_in[3]=Wk : provably unused (softmax over singleton axis == 1)
    const float* Wv     = (const float*)d_in[4];
    const float* Wo     = (const float*)d_in[5];
    const float* ln1g   = (const float*)d_in[6];
    const float* ln1b   = (const float*)d_in[7];
    const float* ln2g   = (const float*)d_in[8];
    const float* ln2b   = (const float*)d_in[9];
    const float* fc1w   = (const float*)d_in[10];
    const float* fc1b   = (const float*)d_in[11];
    const float* fc2w   = (const float*)d_in[12];
    const float* fc2b   = (const float*)d_in[13];
    float* out = (float*)d_out;

    float *xcf, *sbuf, *vbuf, *vcum, *s2, *hbuf, *part, *bs, *st1, *st2;
    cudaGetSymbolAddress((void**)&xcf,  g_xcf);
    cudaGetSymbolAddress((void**)&sbuf, g_s);
    cudaGetSymbolAddress((void**)&vbuf, g_v);
    cudaGetSymbolAddress((void**)&vcum, g_vcum);
    cudaGetSymbolAddress((void**)&s2,   g_s2);
    cudaGetSymbolAddress((void**)&hbuf, g_h);
    cudaGetSymbolAddress((void**)&part, g_part);
    cudaGetSymbolAddress((void**)&bs,   g_bs);
    cudaGetSymbolAddress((void**)&st1,  g_st1);
    cudaGetSymbolAddress((void**)&st2,  g_st2);

    const size_t WSLAB = (size_t)MDIM * MDIM;   // per-block slab in Wv / Wo

    reduce_x_k<<<256, 256>>>(x, xcf);

    // s0 = xcf @ weight^T  (SK=64) ; +pos bias ; LN1 stats
    gemm2_k<0><<<dim3(8, 64), 128>>>(xcf, weight, part, MDIM, MDIM, 0, 0, 0);
    combine_k<64, 1><<<dim3(8, NTOK), 256>>>(part, nullptr, sbuf, bs, MDIM);
    stats_k<<<1, 32>>>(bs, st1);

    for (int a = 0; a < 3; ++a) {
        // V = LN1(s) @ Wv[a]^T
        gemm2_k<1><<<dim3(8, 64), 128>>>(sbuf, Wv + a * WSLAB, part, MDIM, MDIM,
                                         st1, ln1g, ln1b);
        combine_k<64, 4><<<dim3(8, NTOK), 256>>>(part, nullptr, vbuf, nullptr, MDIM);
        prefix_k<<<8, 256>>>(vbuf, vcum);
        // s2 = vcum @ Wo[a]^T + s ; LN2 stats
        gemm2_k<0><<<dim3(8, 64), 128>>>(vcum, Wo + a * WSLAB, part, MDIM, MDIM, 0, 0, 0);
        combine_k<64, 2><<<dim3(8, NTOK), 256>>>(part, sbuf, s2, bs, MDIM);
        stats_k<<<1, 32>>>(bs, st2);
        // h = gelu( (LN2(s2)+s2) @ fc1^T + b1 )   (SK=16)
        gemm2_k<2><<<dim3(32, 16), 128>>>(s2, fc1w, part, HDIM, MDIM, st2, ln2g, ln2b);
        combine_k<16, 3><<<dim3(32, NTOK), 256>>>(part, fc1b, hbuf, nullptr, HDIM);
        // s_next = h @ fc2^T + b2   (SK=64) ; LN1 stats for next block
        gemm2_k<0><<<dim3(8, 64), 128>>>(hbuf, fc2w, part, MDIM, HDIM, 0, 0, 0);
        combine_k<64, 0><<<dim3(8, NTOK), 256>>>(part, fc2b, (a == 2) ? out : sbuf, bs, MDIM);
        if (a < 2) stats_k<<<1, 32>>>(bs, st1);
    }
    (void)in_sizes; (void)n_in; (void)out_size;
}

// round 7
// speedup vs baseline: 3.4995x; 1.1175x over previous
#include <cuda_runtime.h>
#include <cuda_bf16.h>
#include <math.h>

// ---------------------------------------------------------------------------
// Problem constants
// ---------------------------------------------------------------------------
#define NTOK 32          // tokens
#define MDIM 2048
#define HDIM 8192
#define KC   32          // K per smem chunk (elements)

typedef unsigned long long ull;
typedef unsigned int u32;

__device__ __forceinline__ u32 smem_u32(const void* p) {
    u32 a;
    asm("{ .reg .u64 t; cvta.to.shared.u64 t, %1; cvt.u32.u64 %0, t; }" : "=r"(a) : "l"(p));
    return a;
}
__device__ __forceinline__ void ldsm4(u32& r0, u32& r1, u32& r2, u32& r3, u32 addr) {
    asm volatile("ldmatrix.sync.aligned.m8n8.x4.shared.b16 {%0,%1,%2,%3}, [%4];"
                 : "=r"(r0), "=r"(r1), "=r"(r2), "=r"(r3) : "r"(addr));
}
__device__ __forceinline__ void mma_bf16(float* d, const u32* a, const u32* b) {
    asm volatile(
        "mma.sync.aligned.m16n8k16.row.col.f32.bf16.bf16.f32 "
        "{%0,%1,%2,%3}, {%4,%5,%6,%7}, {%8,%9}, {%0,%1,%2,%3};"
        : "+f"(d[0]), "+f"(d[1]), "+f"(d[2]), "+f"(d[3])
        : "r"(a[0]), "r"(a[1]), "r"(a[2]), "r"(a[3]), "r"(b[0]), "r"(b[1]));
}
__device__ __forceinline__ void sts64(u32 addr, ull v) {
    asm volatile("st.shared.b64 [%0], %1;" :: "r"(addr), "l"(v) : "memory");
}
// pack 4 bf16 (round-nearest) into a ull; also produce bf16 lo residual
__device__ __forceinline__ void split4(const float* v, ull& hi4, ull& lo4) {
    u32 h01, h23, l01, l23;
    __nv_bfloat16 h0 = __float2bfloat16_rn(v[0]);
    __nv_bfloat16 h1 = __float2bfloat16_rn(v[1]);
    __nv_bfloat16 h2 = __float2bfloat16_rn(v[2]);
    __nv_bfloat16 h3 = __float2bfloat16_rn(v[3]);
    __nv_bfloat16 l0 = __float2bfloat16_rn(v[0] - __bfloat162float(h0));
    __nv_bfloat16 l1 = __float2bfloat16_rn(v[1] - __bfloat162float(h1));
    __nv_bfloat16 l2 = __float2bfloat16_rn(v[2] - __bfloat162float(h2));
    __nv_bfloat16 l3 = __float2bfloat16_rn(v[3] - __bfloat162float(h3));
    h01 = (u32)__bfloat16_as_ushort(h0) | ((u32)__bfloat16_as_ushort(h1) << 16);
    h23 = (u32)__bfloat16_as_ushort(h2) | ((u32)__bfloat16_as_ushort(h3) << 16);
    l01 = (u32)__bfloat16_as_ushort(l0) | ((u32)__bfloat16_as_ushort(l1) << 16);
    l23 = (u32)__bfloat16_as_ushort(l2) | ((u32)__bfloat16_as_ushort(l3) << 16);
    asm("mov.b64 %0, {%1,%2};" : "=l"(hi4) : "r"(h01), "r"(h23));
    asm("mov.b64 %0, {%1,%2};" : "=l"(lo4) : "r"(l01), "r"(l23));
}

// ---------------------------------------------------------------------------
// Scratch
// ---------------------------------------------------------------------------
__device__ float g_xcf [NTOK * MDIM];
__device__ float g_s   [NTOK * MDIM];
__device__ float g_vcum[NTOK * MDIM];
__device__ float g_s2  [NTOK * MDIM];
__device__ float g_h   [NTOK * HDIM];
__device__ float g_part[32 * NTOK * MDIM];   // == 8 * NTOK * HDIM
__device__ float g_bs  [NTOK * 8 * 2];       // per-(row, col-chunk) sum / sumsq

// ---------------------------------------------------------------------------
// reduce_x: x (16,128,512) -> xcf[32][2048]
// ---------------------------------------------------------------------------
__global__ void reduce_x_k(const float* __restrict__ x, float* __restrict__ xcf) {
    int o = blockIdx.x * blockDim.x + threadIdx.x;
    int i = o >> 11, m = o & 2047, b = m >> 4, a = m & 15;
    const float* p = x + a * (128 * 512) + b * 512 + i * 16;
    float s = 0.f;
#pragma unroll
    for (int t = 0; t < 16; ++t) s += p[t];
    xcf[o] = s * (1.f / 16.f);
}

// ---------------------------------------------------------------------------
// HMMA GEMM: part[slot][32][N] = X[32][Kslice] @ W[Ntile][Kslice]^T
//   XF: 0 raw X | 1 LN1(x) | 2 LN2(x)+x   (stats finalized from bs in-kernel)
// CTA: 128 thr / 4 warps. Tile: 128 weight rows (M) x 32 tokens (N).
// fp32 -> bf16 hi/lo on the fly; 3 mma terms: WhXh + WhXl + WlXh.
// grid = (N/128, SK), klen = K/SK (multiple of KC=32).
// Warp w owns rows [w*32, w*32+32); fragments via ldmatrix (pitch-40 rows,
// conflict-free). Epilogue transposes via smem for coalesced stores.
// ---------------------------------------------------------------------------
template<int XF>
__global__ void __launch_bounds__(128) tgemm_k(
        const float* __restrict__ X, const float* __restrict__ W,
        float* __restrict__ C, int N, int K,
        const float* __restrict__ bsums, const float* __restrict__ lg,
        const float* __restrict__ lb)
{
    __shared__ __align__(16) char raw[25600];
    __shared__ float sh_st[NTOK][2];

    const int tid  = threadIdx.x;
    const int wid  = tid >> 5;
    const int lane = tid & 31;
    const u32 sb  = smem_u32(raw);
    const u32 WHI = sb, WLO = sb + 10240, XHI = sb + 20480, XLO = sb + 23040;
    float* stg = (float*)raw;

    const int n0   = blockIdx.x * 128;
    const int klen = K / gridDim.y;
    const int kbeg = blockIdx.y * klen;
    const int nch  = klen / KC;

    if (XF && tid < 32) {                  // finalize LN stats from combine partials
        float S = 0.f, Q = 0.f;
#pragma unroll
        for (int i = 0; i < 8; ++i) {
            S += bsums[(tid * 8 + i) * 2];
            Q += bsums[(tid * 8 + i) * 2 + 1];
        }
        float m = S * (1.f / (float)MDIM);
        float var = Q * (1.f / (float)MDIM) - m * m;
        sh_st[tid][0] = m;
        sh_st[tid][1] = rsqrtf(var + 1e-5f);
    }

    float acc[2][4][4];
#pragma unroll
    for (int mt = 0; mt < 2; ++mt)
#pragma unroll
        for (int nt = 0; nt < 4; ++nt)
#pragma unroll
            for (int r = 0; r < 4; ++r) acc[mt][nt][r] = 0.f;

    for (int c = 0; c < nch; ++c) {
        const int k0 = kbeg + c * KC;
        // ---- issue global loads (overlap with other CTAs' compute) ----
        float4 wb[8];
#pragma unroll
        for (int p = 0; p < 8; ++p) {
            int idx = tid + p * 128;              // 1024 float4 = 128 rows x 8
            int row = idx >> 3, c4 = idx & 7;
            wb[p] = *(const float4*)(W + (size_t)(n0 + row) * K + k0 + c4 * 4);
        }
        float4 xb[2];
#pragma unroll
        for (int p = 0; p < 2; ++p) {
            int idx = tid + p * 128;              // 256 float4 = 32 rows x 8
            int row = idx >> 3, c4 = idx & 7;
            xb[p] = *(const float4*)(X + (size_t)row * K + k0 + c4 * 4);
        }
        __syncthreads();                          // prev chunk compute done
        // ---- convert + store W (pitch 40 bf16) ----
#pragma unroll
        for (int p = 0; p < 8; ++p) {
            int idx = tid + p * 128;
            int row = idx >> 3, c4 = idx & 7;
            u32 off = (u32)(row * 40 + c4 * 4) * 2;
            ull hi4, lo4;
            split4((const float*)&wb[p], hi4, lo4);
            sts64(WHI + off, hi4);
            sts64(WLO + off, lo4);
        }
        // ---- convert + store X (fused LN) ----
#pragma unroll
        for (int p = 0; p < 2; ++p) {
            int idx = tid + p * 128;
            int row = idx >> 3, c4 = idx & 7;
            float v[4];
            v[0] = xb[p].x; v[1] = xb[p].y; v[2] = xb[p].z; v[3] = xb[p].w;
            if (XF) {
                float mn = sh_st[row][0], rs = sh_st[row][1];
#pragma unroll
                for (int e = 0; e < 4; ++e) {
                    float xn = (v[e] - mn) * rs * lg[k0 + c4 * 4 + e] + lb[k0 + c4 * 4 + e];
                    v[e] = (XF == 2) ? (xn + v[e]) : xn;
                }
            }
            u32 off = (u32)(row * 40 + c4 * 4) * 2;
            ull hi4, lo4;
            split4(v, hi4, lo4);
            sts64(XHI + off, hi4);
            sts64(XLO + off, lo4);
        }
        __syncthreads();
        // ---- compute: 2 K-steps x (2 mtiles x 4 ntiles x 3 terms) mma ----
#pragma unroll
        for (int ks = 0; ks < 2; ++ks) {
            const u32 aoff = (u32)(((wid * 32) + (lane & 15)) * 40 + ks * 16 + (lane >> 4) * 8) * 2;
            u32 ah[2][4], al[2][4];
#pragma unroll
            for (int mt = 0; mt < 2; ++mt) {
                u32 ao = aoff + (u32)(mt * 16 * 40) * 2;
                ldsm4(ah[mt][0], ah[mt][1], ah[mt][2], ah[mt][3], WHI + ao);
                ldsm4(al[mt][0], al[mt][1], al[mt][2], al[mt][3], WLO + ao);
            }
            const u32 boff = (u32)(((lane >> 4) * 8 + (lane & 7)) * 40 +
                                   ks * 16 + ((lane >> 3) & 1) * 8) * 2;
            u32 bh[2][4], bl[2][4];
#pragma unroll
            for (int pr = 0; pr < 2; ++pr) {
                u32 bo = boff + (u32)(pr * 16 * 40) * 2;
                ldsm4(bh[pr][0], bh[pr][1], bh[pr][2], bh[pr][3], XHI + bo);
                ldsm4(bl[pr][0], bl[pr][1], bl[pr][2], bl[pr][3], XLO + bo);
            }
#pragma unroll
            for (int mt = 0; mt < 2; ++mt)
#pragma unroll
                for (int nt = 0; nt < 4; ++nt) {
                    const u32* bhp = &bh[nt >> 1][(nt & 1) * 2];
                    const u32* blp = &bl[nt >> 1][(nt & 1) * 2];
                    mma_bf16(acc[mt][nt], ah[mt], bhp);
                    mma_bf16(acc[mt][nt], ah[mt], blp);
                    mma_bf16(acc[mt][nt], al[mt], bhp);
                }
        }
    }

    // ---- epilogue: transpose via smem, coalesced global stores ----
    __syncthreads();
    {
        const int g = lane >> 2, t2 = (lane & 3) * 2;
#pragma unroll
        for (int mt = 0; mt < 2; ++mt)
#pragma unroll
            for (int nt = 0; nt < 4; ++nt) {
                int row = wid * 32 + mt * 16 + g;
                int tok = nt * 8 + t2;
                stg[tok * 132 + row]           = acc[mt][nt][0];
                stg[(tok + 1) * 132 + row]     = acc[mt][nt][1];
                stg[tok * 132 + row + 8]       = acc[mt][nt][2];
                stg[(tok + 1) * 132 + row + 8] = acc[mt][nt][3];
            }
    }
    __syncthreads();
    float* Cb = C + (size_t)blockIdx.y * ((size_t)NTOK * N);
#pragma unroll
    for (int t = 0; t < NTOK; ++t)
        Cb[(size_t)t * N + n0 + tid] = stg[t * 132 + tid];
}

// ---------------------------------------------------------------------------
// combine: out[row][c] = sum_p parts[p][row][c] (+ MODE epilogue)
//   0:+bias (+stats) | 1:+pos bias (+stats) | 2:+resid (+stats) | 3:+bias,GELU
// grid = (N/256, 32), 256 thr.
// ---------------------------------------------------------------------------
template<int SK, int MODE>
__global__ void combine_k(const float* __restrict__ parts, const float* __restrict__ extra,
                          float* __restrict__ outp, float* __restrict__ bsums, int N)
{
    const int row = blockIdx.y;
    const int c   = blockIdx.x * 256 + threadIdx.x;
    const size_t slot = (size_t)NTOK * N;
    const size_t base = (size_t)row * N + c;

    float v = 0.f;
#pragma unroll 8
    for (int p = 0; p < SK; ++p) v += parts[p * slot + base];

    if (MODE == 0) {
        v += extra[c];
    } else if (MODE == 1) {
        float iv  = exp2f(-(float)(c & ~1) * 0.012976281620653759f);
        float ang = (float)row * iv;
        v += (c & 1) ? cosf(ang) : sinf(ang);
    } else if (MODE == 2) {
        v += extra[base];
    } else if (MODE == 3) {
        v += extra[c];
        v = 0.5f * v * (1.f + erff(v * 0.70710678118f));
    }
    outp[base] = v;

    if (MODE <= 2) {
        float s = v, q = v * v;
#pragma unroll
        for (int off = 16; off; off >>= 1) {
            s += __shfl_down_sync(0xffffffffu, s, off);
            q += __shfl_down_sync(0xffffffffu, q, off);
        }
        __shared__ float rs[8], rq[8];
        if ((threadIdx.x & 31) == 0) { rs[threadIdx.x >> 5] = s; rq[threadIdx.x >> 5] = q; }
        __syncthreads();
        if (threadIdx.x == 0) {
            float S = 0.f, Q = 0.f;
#pragma unroll
            for (int i = 0; i < 8; ++i) { S += rs[i]; Q += rq[i]; }
            bsums[(row * gridDim.x + blockIdx.x) * 2]     = S;
            bsums[(row * gridDim.x + blockIdx.x) * 2 + 1] = Q;
        }
    }
}

// fused split-K combine + token prefix-sum for the V path:
// vcum[i][k] = sum_{j<=i} sum_p part[p][j][k]
__global__ void prefix32_k(const float* __restrict__ parts, float* __restrict__ vc) {
    int k = blockIdx.x * 256 + threadIdx.x;     // 2048
    const size_t slot = (size_t)NTOK * MDIM;
    float acc = 0.f;
    for (int i = 0; i < NTOK; ++i) {
        float v = 0.f;
#pragma unroll
        for (int p = 0; p < 32; ++p) v += parts[p * slot + i * MDIM + k];
        acc += v;
        vc[i * MDIM + k] = acc;
    }
}

// ---------------------------------------------------------------------------
// launch
// ---------------------------------------------------------------------------
extern "C" void kernel_launch(void* const* d_in, const int* in_sizes, int n_in,
                              void* d_out, int out_size)
{
    const float* x      = (const float*)d_in[0];
    const float* weight = (const float*)d_in[1];
    // d_in[2]=Wq, d_in[3]=Wk unused (softmax over singleton axis == 1)
    const float* Wv     = (const float*)d_in[4];
    const float* Wo     = (const float*)d_in[5];
    const float* ln1g   = (const float*)d_in[6];
    const float* ln1b   = (const float*)d_in[7];
    const float* ln2g   = (const float*)d_in[8];
    const float* ln2b   = (const float*)d_in[9];
    const float* fc1w   = (const float*)d_in[10];
    const float* fc1b   = (const float*)d_in[11];
    const float* fc2w   = (const float*)d_in[12];
    const float* fc2b   = (const float*)d_in[13];
    float* out = (float*)d_out;

    float *xcf, *sbuf, *vcum, *s2, *hbuf, *part, *bs;
    cudaGetSymbolAddress((void**)&xcf,  g_xcf);
    cudaGetSymbolAddress((void**)&sbuf, g_s);
    cudaGetSymbolAddress((void**)&vcum, g_vcum);
    cudaGetSymbolAddress((void**)&s2,   g_s2);
    cudaGetSymbolAddress((void**)&hbuf, g_h);
    cudaGetSymbolAddress((void**)&part, g_part);
    cudaGetSymbolAddress((void**)&bs,   g_bs);

    const size_t WSLAB = (size_t)MDIM * MDIM;

    reduce_x_k<<<256, 256>>>(x, xcf);

    // s0 = xcf @ weight^T ; +pos bias ; LN1 stat partials
    tgemm_k<0><<<dim3(16, 32), 128>>>(xcf, weight, part, MDIM, MDIM, 0, 0, 0);
    combine_k<32, 1><<<dim3(8, NTOK), 256>>>(part, nullptr, sbuf, bs, MDIM);

    for (int a = 0; a < 3; ++a) {
        // V = LN1(s) @ Wv[a]^T ; fused combine+prefix -> vcum
        tgemm_k<1><<<dim3(16, 32), 128>>>(sbuf, Wv + a * WSLAB, part, MDIM, MDIM,
                                          bs, ln1g, ln1b);
        prefix32_k<<<8, 256>>>(part, vcum);
        // s2 = vcum @ Wo[a]^T + s ; LN2 stat partials
        tgemm_k<0><<<dim3(16, 32), 128>>>(vcum, Wo + a * WSLAB, part, MDIM, MDIM, 0, 0, 0);
        combine_k<32, 2><<<dim3(8, NTOK), 256>>>(part, sbuf, s2, bs, MDIM);
        // h = gelu( (LN2(s2)+s2) @ fc1^T + b1 )
        tgemm_k<2><<<dim3(64, 8), 128>>>(s2, fc1w, part, HDIM, MDIM, bs, ln2g, ln2b);
        combine_k<8, 3><<<dim3(32, NTOK), 256>>>(part, fc1b, hbuf, nullptr, HDIM);
        // s_next = h @ fc2^T + b2 ; LN1 stat partials for next block
        tgemm_k<0><<<dim3(16, 32), 128>>>(hbuf, fc2w, part, MDIM, HDIM, 0, 0, 0);
        combine_k<32, 0><<<dim3(8, NTOK), 256>>>(part, fc2b, (a == 2) ? out : sbuf, bs, MDIM);
    }
    (void)in_sizes; (void)n_in; (void)out_size;
}

// round 9
// speedup vs baseline: 4.6895x; 1.3401x over previous
#include <cuda_runtime.h>
#include <cuda_bf16.h>
#include <math.h>

// ---------------------------------------------------------------------------
// Problem constants
// ---------------------------------------------------------------------------
#define NTOK 32          // tokens
#define MDIM 2048
#define HDIM 8192
#define KC   32          // K per smem chunk (elements)

typedef unsigned long long ull;
typedef unsigned int u32;

__device__ __forceinline__ u32 smem_u32(const void* p) {
    u32 a;
    asm("{ .reg .u64 t; cvta.to.shared.u64 t, %1; cvt.u32.u64 %0, t; }" : "=r"(a) : "l"(p));
    return a;
}
__device__ __forceinline__ void ldsm4(u32& r0, u32& r1, u32& r2, u32& r3, u32 addr) {
    asm volatile("ldmatrix.sync.aligned.m8n8.x4.shared.b16 {%0,%1,%2,%3}, [%4];"
                 : "=r"(r0), "=r"(r1), "=r"(r2), "=r"(r3) : "r"(addr));
}
__device__ __forceinline__ void mma_bf16(float* d, const u32* a, const u32* b) {
    asm volatile(
        "mma.sync.aligned.m16n8k16.row.col.f32.bf16.bf16.f32 "
        "{%0,%1,%2,%3}, {%4,%5,%6,%7}, {%8,%9}, {%0,%1,%2,%3};"
        : "+f"(d[0]), "+f"(d[1]), "+f"(d[2]), "+f"(d[3])
        : "r"(a[0]), "r"(a[1]), "r"(a[2]), "r"(a[3]), "r"(b[0]), "r"(b[1]));
}
__device__ __forceinline__ void sts64(u32 addr, ull v) {
    asm volatile("st.shared.b64 [%0], %1;" :: "r"(addr), "l"(v) : "memory");
}
// pack 4 bf16 (round-nearest) into a ull; also produce bf16 lo residual
__device__ __forceinline__ void split4(const float* v, ull& hi4, ull& lo4) {
    u32 h01, h23, l01, l23;
    __nv_bfloat16 h0 = __float2bfloat16_rn(v[0]);
    __nv_bfloat16 h1 = __float2bfloat16_rn(v[1]);
    __nv_bfloat16 h2 = __float2bfloat16_rn(v[2]);
    __nv_bfloat16 h3 = __float2bfloat16_rn(v[3]);
    __nv_bfloat16 l0 = __float2bfloat16_rn(v[0] - __bfloat162float(h0));
    __nv_bfloat16 l1 = __float2bfloat16_rn(v[1] - __bfloat162float(h1));
    __nv_bfloat16 l2 = __float2bfloat16_rn(v[2] - __bfloat162float(h2));
    __nv_bfloat16 l3 = __float2bfloat16_rn(v[3] - __bfloat162float(h3));
    h01 = (u32)__bfloat16_as_ushort(h0) | ((u32)__bfloat16_as_ushort(h1) << 16);
    h23 = (u32)__bfloat16_as_ushort(h2) | ((u32)__bfloat16_as_ushort(h3) << 16);
    l01 = (u32)__bfloat16_as_ushort(l0) | ((u32)__bfloat16_as_ushort(l1) << 16);
    l23 = (u32)__bfloat16_as_ushort(l2) | ((u32)__bfloat16_as_ushort(l3) << 16);
    asm("mov.b64 %0, {%1,%2};" : "=l"(hi4) : "r"(h01), "r"(h23));
    asm("mov.b64 %0, {%1,%2};" : "=l"(lo4) : "r"(l01), "r"(l23));
}

// ---------------------------------------------------------------------------
// Scratch
// ---------------------------------------------------------------------------
__device__ float g_xcf [NTOK * MDIM];
__device__ float g_s   [NTOK * MDIM];
__device__ float g_v   [NTOK * MDIM];
__device__ float g_vcum[NTOK * MDIM];
__device__ float g_s2  [NTOK * MDIM];
__device__ float g_h   [NTOK * HDIM];
__device__ float g_part[16 * NTOK * MDIM];   // == 4 * NTOK * HDIM  (4 MB)
__device__ float g_bs  [NTOK * 8 * 2];       // per-(row, col-chunk) sum / sumsq

// ---------------------------------------------------------------------------
// reduce_x: x (16,128,512) -> xcf[32][2048]
// ---------------------------------------------------------------------------
__global__ void reduce_x_k(const float* __restrict__ x, float* __restrict__ xcf) {
    int o = blockIdx.x * blockDim.x + threadIdx.x;
    int i = o >> 11, m = o & 2047, b = m >> 4, a = m & 15;
    const float* p = x + a * (128 * 512) + b * 512 + i * 16;
    float s = 0.f;
#pragma unroll
    for (int t = 0; t < 16; ++t) s += p[t];
    xcf[o] = s * (1.f / 16.f);
}

// ---------------------------------------------------------------------------
// HMMA GEMM: part[slot][32][N] = X[32][Kslice] @ W[Ntile][Kslice]^T
//   XF: 0 raw X | 1 LN1(x) | 2 LN2(x)+x   (stats finalized from bs in-kernel)
// CTA: 128 thr / 4 warps. Tile: 64 weight rows (M) x 32 tokens (N);
// warp w owns rows [w*16, w*16+16). fp32 -> bf16 hi/lo on the fly; 3 mma
// terms WhXh + WhXl + WlXh. Register-prefetch pipeline: chunk c+1's LDGs
// are issued before chunk c's MMAs so DRAM latency hides behind compute.
// grid = (N/64, SK), klen = K/SK (multiple of KC=32).
// ---------------------------------------------------------------------------
template<int XF>
__global__ void __launch_bounds__(128) tgemm_k(
        const float* __restrict__ X, const float* __restrict__ W,
        float* __restrict__ C, int N, int K,
        const float* __restrict__ bsums, const float* __restrict__ lg,
        const float* __restrict__ lb)
{
    __shared__ __align__(16) char raw[15360];
    __shared__ float sh_st[NTOK][2];

    const int tid  = threadIdx.x;
    const int wid  = tid >> 5;
    const int lane = tid & 31;
    const u32 sb  = smem_u32(raw);
    const u32 WHI = sb, WLO = sb + 5120, XHI = sb + 10240, XLO = sb + 12800;
    float* stg = (float*)raw;

    const int n0   = blockIdx.x * 64;
    const int klen = K / gridDim.y;
    const int kbeg = blockIdx.y * klen;
    const int nch  = klen / KC;

    if (XF && tid < 32) {                  // finalize LN stats from combine partials
        float S = 0.f, Q = 0.f;
#pragma unroll
        for (int i = 0; i < 8; ++i) {
            S += bsums[(tid * 8 + i) * 2];
            Q += bsums[(tid * 8 + i) * 2 + 1];
        }
        float m = S * (1.f / (float)MDIM);
        float var = Q * (1.f / (float)MDIM) - m * m;
        sh_st[tid][0] = m;
        sh_st[tid][1] = rsqrtf(var + 1e-5f);
    }

    float acc[4][4];
#pragma unroll
    for (int nt = 0; nt < 4; ++nt)
#pragma unroll
        for (int r = 0; r < 4; ++r) acc[nt][r] = 0.f;

    const int lrow = tid >> 3;            // 0..15
    const int lc4  = tid & 7;

    float4 wb[4], xb[2];
    auto LOAD = [&](int k0) {
#pragma unroll
        for (int p = 0; p < 4; ++p) {
            int row = lrow + p * 16;                      // 64 rows x 8 c4
            wb[p] = *(const float4*)(W + (size_t)(n0 + row) * K + k0 + lc4 * 4);
        }
#pragma unroll
        for (int p = 0; p < 2; ++p) {
            int row = lrow + p * 16;                      // 32 rows x 8 c4
            xb[p] = *(const float4*)(X + (size_t)row * K + k0 + lc4 * 4);
        }
    };

    LOAD(kbeg);
    for (int c = 0; c < nch; ++c) {
        const int k0 = kbeg + c * KC;
        __syncthreads();                       // smem consumers of chunk c-1 done
        // ---- convert + store W (pitch 40 bf16) ----
#pragma unroll
        for (int p = 0; p < 4; ++p) {
            int row = lrow + p * 16;
            u32 off = (u32)(row * 40 + lc4 * 4) * 2;
            ull hi4, lo4;
            split4((const float*)&wb[p], hi4, lo4);
            sts64(WHI + off, hi4);
            sts64(WLO + off, lo4);
        }
        // ---- convert + store X (fused LN) ----
#pragma unroll
        for (int p = 0; p < 2; ++p) {
            int row = lrow + p * 16;
            float v[4];
            v[0] = xb[p].x; v[1] = xb[p].y; v[2] = xb[p].z; v[3] = xb[p].w;
            if (XF) {
                float mn = sh_st[row][0], rs = sh_st[row][1];
#pragma unroll
                for (int e = 0; e < 4; ++e) {
                    float xn = (v[e] - mn) * rs * lg[k0 + lc4 * 4 + e] + lb[k0 + lc4 * 4 + e];
                    v[e] = (XF == 2) ? (xn + v[e]) : xn;
                }
            }
            u32 off = (u32)(row * 40 + lc4 * 4) * 2;
            ull hi4, lo4;
            split4(v, hi4, lo4);
            sts64(XHI + off, hi4);
            sts64(XLO + off, lo4);
        }
        __syncthreads();
        // ---- prefetch next chunk's globals (overlaps with MMAs below) ----
        if (c + 1 < nch) LOAD(k0 + KC);
        // ---- compute: 2 K-steps x (4 ntiles x 3 terms) mma ----
#pragma unroll
        for (int ks = 0; ks < 2; ++ks) {
            const u32 aoff = (u32)((wid * 16 + (lane & 15)) * 40 +
                                   ks * 16 + (lane >> 4) * 8) * 2;
            u32 ah[4], al[4];
            ldsm4(ah[0], ah[1], ah[2], ah[3], WHI + aoff);
            ldsm4(al[0], al[1], al[2], al[3], WLO + aoff);
            const u32 boff = (u32)(((lane >> 4) * 8 + (lane & 7)) * 40 +
                                   ks * 16 + ((lane >> 3) & 1) * 8) * 2;
            u32 bh[2][4], bl[2][4];
#pragma unroll
            for (int pr = 0; pr < 2; ++pr) {
                u32 bo = boff + (u32)(pr * 16 * 40) * 2;
                ldsm4(bh[pr][0], bh[pr][1], bh[pr][2], bh[pr][3], XHI + bo);
                ldsm4(bl[pr][0], bl[pr][1], bl[pr][2], bl[pr][3], XLO + bo);
            }
#pragma unroll
            for (int nt = 0; nt < 4; ++nt) {
                const u32* bhp = &bh[nt >> 1][(nt & 1) * 2];
                const u32* blp = &bl[nt >> 1][(nt & 1) * 2];
                mma_bf16(acc[nt], ah, bhp);
                mma_bf16(acc[nt], ah, blp);
                mma_bf16(acc[nt], al, bhp);
            }
        }
    }

    // ---- epilogue: transpose via smem, coalesced global stores ----
    __syncthreads();
    {
        const int g = lane >> 2, t2 = (lane & 3) * 2;
        const int row = wid * 16 + g;
#pragma unroll
        for (int nt = 0; nt < 4; ++nt) {
            int tok = nt * 8 + t2;
            stg[tok * 68 + row]           = acc[nt][0];
            stg[(tok + 1) * 68 + row]     = acc[nt][1];
            stg[tok * 68 + row + 8]       = acc[nt][2];
            stg[(tok + 1) * 68 + row + 8] = acc[nt][3];
        }
    }
    __syncthreads();
    float* Cb = C + (size_t)blockIdx.y * ((size_t)NTOK * N);
    const int tok0 = tid >> 6, col = tid & 63;
#pragma unroll
    for (int t = tok0; t < NTOK; t += 2)
        Cb[(size_t)t * N + n0 + col] = stg[t * 68 + col];
}

// ---------------------------------------------------------------------------
// combine: out[row][c] = sum_p parts[p][row][c] (+ MODE epilogue)
//   0:+bias (+stats) | 1:+pos bias (+stats) | 2:+resid (+stats)
//   3:+bias,GELU | 4: plain
// grid = (N/256, 32), 256 thr.
// ---------------------------------------------------------------------------
template<int SK, int MODE>
__global__ void combine_k(const float* __restrict__ parts, const float* __restrict__ extra,
                          float* __restrict__ outp, float* __restrict__ bsums, int N)
{
    const int row = blockIdx.y;
    const int c   = blockIdx.x * 256 + threadIdx.x;
    const size_t slot = (size_t)NTOK * N;
    const size_t base = (size_t)row * N + c;

    float v = 0.f;
#pragma unroll
    for (int p = 0; p < SK; ++p) v += parts[p * slot + base];

    if (MODE == 0) {
        v += extra[c];
    } else if (MODE == 1) {
        float iv  = exp2f(-(float)(c & ~1) * 0.012976281620653759f);
        float ang = (float)row * iv;
        v += (c & 1) ? cosf(ang) : sinf(ang);
    } else if (MODE == 2) {
        v += extra[base];
    } else if (MODE == 3) {
        v += extra[c];
        v = 0.5f * v * (1.f + erff(v * 0.70710678118f));
    }
    outp[base] = v;

    if (MODE <= 2) {
        float s = v, q = v * v;
#pragma unroll
        for (int off = 16; off; off >>= 1) {
            s += __shfl_down_sync(0xffffffffu, s, off);
            q += __shfl_down_sync(0xffffffffu, q, off);
        }
        __shared__ float rs[8], rq[8];
        if ((threadIdx.x & 31) == 0) { rs[threadIdx.x >> 5] = s; rq[threadIdx.x >> 5] = q; }
        __syncthreads();
        if (threadIdx.x == 0) {
            float S = 0.f, Q = 0.f;
#pragma unroll
            for (int i = 0; i < 8; ++i) { S += rs[i]; Q += rq[i]; }
            bsums[(row * gridDim.x + blockIdx.x) * 2]     = S;
            bsums[(row * gridDim.x + blockIdx.x) * 2 + 1] = Q;
        }
    }
}

// token prefix-sum: vcum[i][k] = sum_{j<=i} V[j][k]
__global__ void prefix_k(const float* __restrict__ V, float* __restrict__ vc) {
    int k = blockIdx.x * 256 + threadIdx.x;
    float acc = 0.f;
#pragma unroll
    for (int i = 0; i < NTOK; ++i) {
        acc += V[i * MDIM + k];
        vc[i * MDIM + k] = acc;
    }
}

// ---------------------------------------------------------------------------
// launch
// ---------------------------------------------------------------------------
extern "C" void kernel_launch(void* const* d_in, const int* in_sizes, int n_in,
                              void* d_out, int out_size)
{
    const float* x      = (const float*)d_in[0];
    const float* weight = (const float*)d_in[1];
    // d_in[2]=Wq, d_in[3]=Wk unused (softmax over singleton axis == 1)
    const float* Wv     = (const float*)d_in[4];
    const float* Wo     = (const float*)d_in[5];
    const float* ln1g   = (const float*)d_in[6];
    const float* ln1b   = (const float*)d_in[7];
    const float* ln2g   = (const float*)d_in[8];
    const float* ln2b   = (const float*)d_in[9];
    const float* fc1w   = (const float*)d_in[10];
    const float* fc1b   = (const float*)d_in[11];
    const float* fc2w   = (const float*)d_in[12];
    const float* fc2b   = (const float*)d_in[13];
    float* out = (float*)d_out;

    float *xcf, *sbuf, *vbuf, *vcum, *s2, *hbuf, *part, *bs;
    cudaGetSymbolAddress((void**)&xcf,  g_xcf);
    cudaGetSymbolAddress((void**)&sbuf, g_s);
    cudaGetSymbolAddress((void**)&vbuf, g_v);
    cudaGetSymbolAddress((void**)&vcum, g_vcum);
    cudaGetSymbolAddress((void**)&s2,   g_s2);
    cudaGetSymbolAddress((void**)&hbuf, g_h);
    cudaGetSymbolAddress((void**)&part, g_part);
    cudaGetSymbolAddress((void**)&bs,   g_bs);

    const size_t WSLAB = (size_t)MDIM * MDIM;

    reduce_x_k<<<256, 256>>>(x, xcf);

    // s0 = xcf @ weight^T ; +pos bias ; LN1 stat partials
    tgemm_k<0><<<dim3(32, 16), 128>>>(xcf, weight, part, MDIM, MDIM, 0, 0, 0);
    combine_k<16, 1><<<dim3(8, NTOK), 256>>>(part, nullptr, sbuf, bs, MDIM);

    for (int a = 0; a < 3; ++a) {
        // V = LN1(s) @ Wv[a]^T ; combine ; prefix -> vcum
        tgemm_k<1><<<dim3(32, 16), 128>>>(sbuf, Wv + a * WSLAB, part, MDIM, MDIM,
                                          bs, ln1g, ln1b);
        combine_k<16, 4><<<dim3(8, NTOK), 256>>>(part, nullptr, vbuf, nullptr, MDIM);
        prefix_k<<<8, 256>>>(vbuf, vcum);
        // s2 = vcum @ Wo[a]^T + s ; LN2 stat partials
        tgemm_k<0><<<dim3(32, 16), 128>>>(vcum, Wo + a * WSLAB, part, MDIM, MDIM, 0, 0, 0);
        combine_k<16, 2><<<dim3(8, NTOK), 256>>>(part, sbuf, s2, bs, MDIM);
        // h = gelu( (LN2(s2)+s2) @ fc1^T + b1 )
        tgemm_k<2><<<dim3(128, 4), 128>>>(s2, fc1w, part, HDIM, MDIM, bs, ln2g, ln2b);
        combine_k<4, 3><<<dim3(32, NTOK), 256>>>(part, fc1b, hbuf, nullptr, HDIM);
        // s_next = h @ fc2^T + b2 ; LN1 stat partials for next block
        tgemm_k<0><<<dim3(32, 16), 128>>>(hbuf, fc2w, part, MDIM, HDIM, 0, 0, 0);
        combine_k<16, 0><<<dim3(8, NTOK), 256>>>(part, fc2b, (a == 2) ? out : sbuf, bs, MDIM);
    }
    (void)in_sizes; (void)n_in; (void)out_size;
}